// round 13
// baseline (speedup 1.0000x reference)
#include <cuda_runtime.h>
#include <cuda_bf16.h>

// Problem constants (fixed by the dataset):
//   acts: (B, T, U+1, V) fp32, labels: (B, U) int32, act_lens/label_lens: (B,) int32
#define BB  16
#define TT  200
#define UU  100
#define VV  256
#define UP1 101          // U + 1
#define NEG_INF (-1e30f)
#define LOG2E 1.4426950408889634f
#define LN2   0.6931471805599453f

// Guarded, padded smem tiles (log2-domain values):
//   sbg row r stores blank[t = r-1][u] * LOG2E, r in [0, TT+1]
//   seg row r stores emit [t = r-1][u-1] * LOG2E (shifted by one in u)
#define SBP  104                 // padded pitch (multiple of 4)
#define SEP  104
#define ROWS (TT + 2)            // 202
#define SMEM_FLOATS (ROWS * SBP + ROWS * SEP)   // 42,016 floats = 168,064 B

// Scratch (no cudaMalloc allowed).
__device__ float    g_blank[BB * TT * UP1];   // (B, T, U+1)
__device__ float    g_emit [BB * TT * UU];    // (B, T, U)
__device__ float    g_perb [BB];              // per-example nll / label_len
__device__ unsigned g_done = 0;               // block-completion counter

// ---------------------------------------------------------------------------
// Kernel 1: fused log-softmax gather, TWO (b,t,u) nodes per warp (MLP=4).
// Skips nodes outside the live lattice region. (Measured at effective-BW
// roofline; 4-node variant regressed on register pressure.)
// ---------------------------------------------------------------------------
__global__ __launch_bounds__(256) void rnnt_softmax_kernel(
    const float* __restrict__ acts,
    const int*   __restrict__ labels,
    const int*   __restrict__ act_lens,
    const int*   __restrict__ label_lens)
{
    const int P = BB * TT * UP1;                       // 323200 (even)
    int w    = blockIdx.x * 8 + (threadIdx.x >> 5);    // warp id
    int lane = threadIdx.x & 31;
    int n0   = w * 2;
    if (n0 >= P) return;
    int n1 = n0 + 1;

    int u0 = n0 % UP1, bt0 = n0 / UP1, t0 = bt0 % TT, b0i = bt0 / TT;
    int u1 = n1 % UP1, bt1 = n1 / UP1, t1 = bt1 % TT, b1i = bt1 / TT;

    bool L0 = (t0 < __ldg(act_lens + b0i)) && (u0 <= __ldg(label_lens + b0i));
    bool L1 = (t1 < __ldg(act_lens + b1i)) && (u1 <= __ldg(label_lens + b1i));
    if (!L0 && !L1) return;

    const float4* p0 = reinterpret_cast<const float4*>(acts) + (size_t)n0 * (VV / 4);
    const float4* p1 = p0 + (VV / 4);

    float4 a0 = {0,0,0,0}, c0 = {0,0,0,0}, a1 = {0,0,0,0}, c1 = {0,0,0,0};
    if (L0) { a0 = p0[lane]; c0 = p0[lane + 32]; }
    if (L1) { a1 = p1[lane]; c1 = p1[lane + 32]; }

    float m0 = fmaxf(fmaxf(fmaxf(a0.x, a0.y), fmaxf(a0.z, a0.w)),
                     fmaxf(fmaxf(c0.x, c0.y), fmaxf(c0.z, c0.w)));
    float m1 = fmaxf(fmaxf(fmaxf(a1.x, a1.y), fmaxf(a1.z, a1.w)),
                     fmaxf(fmaxf(c1.x, c1.y), fmaxf(c1.z, c1.w)));
    #pragma unroll
    for (int o = 16; o; o >>= 1) {
        m0 = fmaxf(m0, __shfl_xor_sync(0xffffffffu, m0, o));
        m1 = fmaxf(m1, __shfl_xor_sync(0xffffffffu, m1, o));
    }

    float s0 = __expf(a0.x - m0) + __expf(a0.y - m0) + __expf(a0.z - m0) + __expf(a0.w - m0)
             + __expf(c0.x - m0) + __expf(c0.y - m0) + __expf(c0.z - m0) + __expf(c0.w - m0);
    float s1 = __expf(a1.x - m1) + __expf(a1.y - m1) + __expf(a1.z - m1) + __expf(a1.w - m1)
             + __expf(c1.x - m1) + __expf(c1.y - m1) + __expf(c1.z - m1) + __expf(c1.w - m1);
    #pragma unroll
    for (int o = 16; o; o >>= 1) {
        s0 += __shfl_xor_sync(0xffffffffu, s0, o);
        s1 += __shfl_xor_sync(0xffffffffu, s1, o);
    }

    if (lane == 0) {
        if (L0) {
            float logZ = m0 + __logf(s0);
            g_blank[n0] = a0.x - logZ;                 // a0.x on lane0 = blank logit
            if (u0 < UU) {
                int lbl  = labels[b0i * UU + u0];
                float lv = __ldg(acts + (size_t)n0 * VV + lbl);
                g_emit[bt0 * UU + u0] = lv - logZ;
            }
        }
        if (L1) {
            float logZ = m1 + __logf(s1);
            g_blank[n1] = a1.x - logZ;
            if (u1 < UU) {
                int lbl  = labels[b1i * UU + u1];
                float lv = __ldg(acts + (size_t)n1 * VV + lbl);
                g_emit[bt1 * UU + u1] = lv - logZ;
            }
        }
    }
}

// log-sum-exp of two values in the log2 domain.
__device__ __forceinline__ float la2(float x, float y)
{
    float mx = fmaxf(x, y);
    float mn = fminf(x, y);
    return mx + __log2f(1.0f + exp2f(mn - mx));
}

// ---------------------------------------------------------------------------
// Kernel 2: per-example forward DP, whole diagonal in ONE warp.
// Lane l owns u in {4l..4l+3} (contiguous). Left-neighbor deps for cells
// k=1..3 come from the lane's own (old) registers; only k=0 needs a single
// shfl_up of the neighbor lane's a3. No barriers, no masks: t-range guard
// rows (t = -1 and t >= Tl) hold NEG_INF, and out-of-range cells compute
// garbage that can never flow into valid cells (deps go up in u, fwd in t).
// Values are staged pre-scaled by LOG2E so the logaddexp chain uses raw
// EX2/LG2 without ln2 fixups. Mean-reduction fused via completion counter.
// ---------------------------------------------------------------------------
__global__ __launch_bounds__(128) void rnnt_dp_kernel(
    const int* __restrict__ act_lens,
    const int* __restrict__ label_lens,
    float*     __restrict__ out)
{
    int b   = blockIdx.x;
    int Tl  = act_lens[b];
    int Ul  = label_lens[b];
    int tid = threadIdx.x;

    extern __shared__ float sm[];
    float* sbg = sm;                  // ROWS * SBP
    float* seg = sm + ROWS * SBP;     // ROWS * SEP

    // Pass 1: NEG_INF fill (guard rows, shifted col 0, padding).
    {
        float4 nf = make_float4(NEG_INF, NEG_INF, NEG_INF, NEG_INF);
        float4* s4 = reinterpret_cast<float4*>(sm);
        for (int i = tid; i < SMEM_FLOATS / 4; i += 128) s4[i] = nf;
    }
    __syncthreads();

    // Pass 2: live rows, scaled into the log2 domain.
    {
        const float* gb = g_blank + (size_t)b * TT * UP1;
        const float* ge = g_emit  + (size_t)b * TT * UU;
        int nb = Tl * UP1;
        int ne = Tl * UU;
        for (int i = tid; i < nb; i += 128) {
            int t = i / UP1, u = i - t * UP1;
            sbg[(t + 1) * SBP + u] = gb[i] * LOG2E;
        }
        for (int i = tid; i < ne; i += 128) {
            int t = i / UU, u = i - t * UU;
            seg[(t + 1) * SEP + (u + 1)] = ge[i] * LOG2E;   // shifted by one in u
        }
    }
    __syncthreads();
    if (tid >= 32) return;

    const unsigned F = 0xffffffffu;
    int l  = tid;
    int u0 = 4 * l;
    // Column clamps (only lanes >= 26 clamp; their cells are garbage anyway).
    int c0 = min(u0,     SBP - 1);
    int c1 = min(u0 + 1, SBP - 1);
    int c2 = min(u0 + 2, SBP - 1);
    int c3 = min(u0 + 3, SBP - 1);

    // alpha[0][u] in log2 domain.
    float a0 = (l == 0) ? 0.0f : NEG_INF;
    float a1 = NEG_INF, a2 = NEG_INF, a3 = NEG_INF;

    int dmax = (Tl - 1) + Ul;
    for (int d = 1; d <= dmax; ++d) {
        float sh = __shfl_up_sync(F, a3, 1);     // alpha[d-1][4l-1]
        if (l == 0) sh = NEG_INF;

        // Row indices: blank for cell k lives at sbg row (d - u0 - k),
        // emit  for cell k lives at seg row (d - u0 - k + 1). Clamps shared.
        int r0  = d - u0;
        int rb0 = min(max(r0,     0), ROWS - 1);
        int rb1 = min(max(r0 - 1, 0), ROWS - 1);
        int rb2 = min(max(r0 - 2, 0), ROWS - 1);
        int rb3 = min(max(r0 - 3, 0), ROWS - 1);
        int re0 = min(max(r0 + 1, 0), ROWS - 1);
        // re1 = rb0, re2 = rb1, re3 = rb2 (index reuse).

        float bv0 = sbg[rb0 * SBP + c0];
        float bv1 = sbg[rb1 * SBP + c1];
        float bv2 = sbg[rb2 * SBP + c2];
        float bv3 = sbg[rb3 * SBP + c3];
        float ev0 = seg[re0 * SEP + c0];
        float ev1 = seg[rb0 * SEP + c1];
        float ev2 = seg[rb1 * SEP + c2];
        float ev3 = seg[rb2 * SEP + c3];

        float n0 = la2(a0 + bv0, sh + ev0);
        float n1 = la2(a1 + bv1, a0 + ev1);
        float n2 = la2(a2 + bv2, a1 + ev2);
        float n3 = la2(a3 + bv3, a2 + ev3);
        a0 = n0; a1 = n1; a2 = n2; a3 = n3;
    }

    // Terminal cell (t = Tl-1, u = Ul) lives in lane Ul>>2, reg Ul&3.
    if (u0 <= Ul && Ul <= u0 + 3) {
        int k = Ul - u0;
        float v = (k == 0) ? a0 : (k == 1) ? a1 : (k == 2) ? a2 : a3;
        float ll2 = v + sbg[Tl * SBP + Ul];      // + blank[Tl-1][Ul] (log2 dom.)
        g_perb[b] = -(ll2 * LN2) / (float)Ul;
        __threadfence();
        unsigned done = atomicAdd(&g_done, 1u);
        if (done == BB - 1) {                    // last example: fold the mean
            __threadfence();
            float s = 0.0f;
            #pragma unroll
            for (int i = 0; i < BB; ++i) s += __ldcg(&g_perb[i]);
            out[0] = s / (float)BB;
            g_done = 0;                          // reset for next graph replay
        }
    }
}

extern "C" void kernel_launch(void* const* d_in, const int* in_sizes, int n_in,
                              void* d_out, int out_size)
{
    const float* acts       = (const float*)d_in[0];
    const int*   labels     = (const int*)  d_in[1];
    const int*   act_lens   = (const int*)  d_in[2];
    const int*   label_lens = (const int*)  d_in[3];
    float*       out        = (float*)d_out;

    const int P     = BB * TT * UP1;          // lattice nodes
    const int pairs = P / 2;                  // two nodes per warp
    int blocks = (pairs + 7) / 8;             // 8 warps per 256-thread block
    rnnt_softmax_kernel<<<blocks, 256>>>(acts, labels, act_lens, label_lens);

    size_t smem = (size_t)SMEM_FLOATS * sizeof(float);   // 168,064 B dynamic
    cudaFuncSetAttribute(rnnt_dp_kernel,
                         cudaFuncAttributeMaxDynamicSharedMemorySize, (int)smem);
    rnnt_dp_kernel<<<BB, 128, smem>>>(act_lens, label_lens, out);
}

// round 14
// speedup vs baseline: 1.3012x; 1.3012x over previous
#include <cuda_runtime.h>
#include <cuda_bf16.h>

// Problem constants (fixed by the dataset):
//   acts: (B, T, U+1, V) fp32, labels: (B, U) int32, act_lens/label_lens: (B,) int32
#define BB  16
#define TT  200
#define UU  100
#define VV  256
#define UP1 101          // U + 1
#define NEG_INF (-1e30f)
#define LOG2E 1.4426950408889634f
#define LN2   0.6931471805599453f

// Guarded smem tiles in the log2 domain, both with pitch UP1 = 101:
//   sbg row r (r = t+1, r in [0, TT+1]) col u     = blank[t][u]   * LOG2E
//   seg row r (r = t+1)                 col (u+1) = emit [t][u]   * LOG2E
// Row 0 (t = -1), rows >= Tl+1, and seg col 0 stay NEG_INF (guards).
#define ROWS (TT + 2)                           // 202
#define SMEM_FLOATS (2 * ROWS * UP1)            // 40,804 floats = 163,216 B

// Scratch (no cudaMalloc allowed).
__device__ float    g_blank[BB * TT * UP1];   // (B, T, U+1)
__device__ float    g_emit [BB * TT * UU];    // (B, T, U)
__device__ float    g_perb [BB];              // per-example nll / label_len
__device__ unsigned g_done = 0;               // block-completion counter

// ---------------------------------------------------------------------------
// Kernel 1: fused log-softmax gather, TWO (b,t,u) nodes per warp (MLP=4).
// Skips nodes outside the live lattice region. (Measured at effective-BW
// roofline; 4-node variant regressed on register pressure.)
// ---------------------------------------------------------------------------
__global__ __launch_bounds__(256) void rnnt_softmax_kernel(
    const float* __restrict__ acts,
    const int*   __restrict__ labels,
    const int*   __restrict__ act_lens,
    const int*   __restrict__ label_lens)
{
    const int P = BB * TT * UP1;                       // 323200 (even)
    int w    = blockIdx.x * 8 + (threadIdx.x >> 5);    // warp id
    int lane = threadIdx.x & 31;
    int n0   = w * 2;
    if (n0 >= P) return;
    int n1 = n0 + 1;

    int u0 = n0 % UP1, bt0 = n0 / UP1, t0 = bt0 % TT, b0i = bt0 / TT;
    int u1 = n1 % UP1, bt1 = n1 / UP1, t1 = bt1 % TT, b1i = bt1 / TT;

    bool L0 = (t0 < __ldg(act_lens + b0i)) && (u0 <= __ldg(label_lens + b0i));
    bool L1 = (t1 < __ldg(act_lens + b1i)) && (u1 <= __ldg(label_lens + b1i));
    if (!L0 && !L1) return;

    const float4* p0 = reinterpret_cast<const float4*>(acts) + (size_t)n0 * (VV / 4);
    const float4* p1 = p0 + (VV / 4);

    float4 a0 = {0,0,0,0}, c0 = {0,0,0,0}, a1 = {0,0,0,0}, c1 = {0,0,0,0};
    if (L0) { a0 = p0[lane]; c0 = p0[lane + 32]; }
    if (L1) { a1 = p1[lane]; c1 = p1[lane + 32]; }

    float m0 = fmaxf(fmaxf(fmaxf(a0.x, a0.y), fmaxf(a0.z, a0.w)),
                     fmaxf(fmaxf(c0.x, c0.y), fmaxf(c0.z, c0.w)));
    float m1 = fmaxf(fmaxf(fmaxf(a1.x, a1.y), fmaxf(a1.z, a1.w)),
                     fmaxf(fmaxf(c1.x, c1.y), fmaxf(c1.z, c1.w)));
    #pragma unroll
    for (int o = 16; o; o >>= 1) {
        m0 = fmaxf(m0, __shfl_xor_sync(0xffffffffu, m0, o));
        m1 = fmaxf(m1, __shfl_xor_sync(0xffffffffu, m1, o));
    }

    float s0 = __expf(a0.x - m0) + __expf(a0.y - m0) + __expf(a0.z - m0) + __expf(a0.w - m0)
             + __expf(c0.x - m0) + __expf(c0.y - m0) + __expf(c0.z - m0) + __expf(c0.w - m0);
    float s1 = __expf(a1.x - m1) + __expf(a1.y - m1) + __expf(a1.z - m1) + __expf(a1.w - m1)
             + __expf(c1.x - m1) + __expf(c1.y - m1) + __expf(c1.z - m1) + __expf(c1.w - m1);
    #pragma unroll
    for (int o = 16; o; o >>= 1) {
        s0 += __shfl_xor_sync(0xffffffffu, s0, o);
        s1 += __shfl_xor_sync(0xffffffffu, s1, o);
    }

    if (lane == 0) {
        if (L0) {
            float logZ = m0 + __logf(s0);
            g_blank[n0] = a0.x - logZ;                 // a0.x on lane0 = blank logit
            if (u0 < UU) {
                int lbl  = labels[b0i * UU + u0];
                float lv = __ldg(acts + (size_t)n0 * VV + lbl);
                g_emit[bt0 * UU + u0] = lv - logZ;
            }
        }
        if (L1) {
            float logZ = m1 + __logf(s1);
            g_blank[n1] = a1.x - logZ;
            if (u1 < UU) {
                int lbl  = labels[b1i * UU + u1];
                float lv = __ldg(acts + (size_t)n1 * VV + lbl);
                g_emit[bt1 * UU + u1] = lv - logZ;
            }
        }
    }
}

// ---------------------------------------------------------------------------
// Kernel 2: per-example forward DP, 4 warps x 1 cell/lane (u = 32*warp+lane),
// one barrier per diagonal (the structure that measured best), with:
//   - software-pipelined smem loads: next diagonal's blank/emit values are
//     loaded BEFORE the barrier (sb/se are read-only), so their latency is
//     absorbed by the barrier wait instead of the alpha chain;
//   - NEG_INF guard rows/cols instead of validity masks (invalid cells only
//     ever feed invalid cells; garbage stays finite over <=299 steps);
//   - log2-domain values (pre-scaled by log2 e) for a shorter logaddexp.
// Cross-warp boundary via a tiny double-buffered smem slot per warp.
// Mean-reduction fused via completion counter.
// ---------------------------------------------------------------------------
__global__ __launch_bounds__(128) void rnnt_dp_kernel(
    const int* __restrict__ act_lens,
    const int* __restrict__ label_lens,
    float*     __restrict__ out)
{
    int b   = blockIdx.x;
    int Tl  = act_lens[b];
    int Ul  = label_lens[b];
    int tid = threadIdx.x;
    int w   = tid >> 5;
    int l   = tid & 31;

    extern __shared__ float sm[];
    float* sbg = sm;                    // ROWS * UP1
    float* seg = sm + ROWS * UP1;       // ROWS * UP1 (emit shifted +1 col)
    __shared__ float bd[2][4];          // [parity][warp] boundary alpha

    // Pass 1: NEG_INF fill (guards everywhere).
    {
        float4 nf = make_float4(NEG_INF, NEG_INF, NEG_INF, NEG_INF);
        float4* s4 = reinterpret_cast<float4*>(sm);
        for (int i = tid; i < SMEM_FLOATS / 4; i += 128) s4[i] = nf;
        if (tid < 8) bd[tid >> 2][tid & 3] = NEG_INF;
    }
    __syncthreads();

    // Pass 2: live rows (t in [0, Tl)), scaled into the log2 domain.
    {
        const float* gb = g_blank + (size_t)b * TT * UP1;
        const float* ge = g_emit  + (size_t)b * TT * UU;
        int nb = Tl * UP1;
        int ne = Tl * UU;
        // blank: dest index = (t+1)*UP1 + u = i + UP1 (contiguous shift).
        for (int i = tid; i < nb; i += 128) sbg[UP1 + i] = gb[i] * LOG2E;
        // emit: dest = (t+1)*UP1 + (u+1) with i = t*UU + u.
        for (int i = tid; i < ne; i += 128) {
            int t = i / UU, u = i - t * UU;
            seg[(t + 1) * UP1 + (u + 1)] = ge[i] * LOG2E;
        }
    }
    __syncthreads();

    const unsigned F = 0xffffffffu;
    int u   = w * 32 + l;                     // fixed u per lane (0..127)
    int ucb = min(u, UU);                     // sbg col (clamp only garbage lanes)
    int uce = min(u, UU);                     // seg col (shifted layout: col u)

    float pp = (u == 0) ? 0.0f : NEG_INF;     // alpha[0][u], log2 domain
    int dmax = (Tl - 1) + Ul;
    int par  = 0;

    // Prefetch diagonal d=1: bv row = d-u, ev row = d-u+1 (clamped to guards).
    int r0 = 1 - u;
    float bv = sbg[min(max(r0,     0), ROWS - 1) * UP1 + ucb];
    float ev = seg[min(max(r0 + 1, 0), ROWS - 1) * UP1 + uce];

    for (int d = 1; d <= dmax; ++d) {
        // Boundary from the left warp (published before last barrier).
        float nb = (w > 0) ? bd[par][w - 1] : NEG_INF;

        float lf = __shfl_up_sync(F, pp, 1);
        lf = (l == 0) ? nb : lf;

        float fb = pp + bv;
        float fl = lf + ev;
        float mx = fmaxf(fb, fl);
        float mn = fminf(fb, fl);
        pp = mx + __log2f(1.0f + exp2f(mn - mx));

        if (l == 31 && w < 3) bd[par ^ 1][w] = pp;

        // Prefetch diagonal d+1 (independent of pp; completes over the BAR).
        int r1 = d + 1 - u;
        bv = sbg[min(max(r1,     0), ROWS - 1) * UP1 + ucb];
        ev = seg[min(max(r1 + 1, 0), ROWS - 1) * UP1 + uce];

        par ^= 1;
        __syncthreads();
    }

    // Terminal cell (t = Tl-1, u = Ul): log-lik = alpha + blank[Tl-1][Ul].
    if (u == Ul) {
        float ll2 = pp + sbg[Tl * UP1 + Ul];     // row Tl = (Tl-1)+1
        g_perb[b] = -(ll2 * LN2) / (float)Ul;
        __threadfence();
        unsigned done = atomicAdd(&g_done, 1u);
        if (done == BB - 1) {                    // last example: fold the mean
            __threadfence();
            float s = 0.0f;
            #pragma unroll
            for (int i = 0; i < BB; ++i) s += __ldcg(&g_perb[i]);
            out[0] = s / (float)BB;
            g_done = 0;                          // reset for next graph replay
        }
    }
}

extern "C" void kernel_launch(void* const* d_in, const int* in_sizes, int n_in,
                              void* d_out, int out_size)
{
    const float* acts       = (const float*)d_in[0];
    const int*   labels     = (const int*)  d_in[1];
    const int*   act_lens   = (const int*)  d_in[2];
    const int*   label_lens = (const int*)  d_in[3];
    float*       out        = (float*)d_out;

    const int P     = BB * TT * UP1;          // lattice nodes
    const int pairs = P / 2;                  // two nodes per warp
    int blocks = (pairs + 7) / 8;             // 8 warps per 256-thread block
    rnnt_softmax_kernel<<<blocks, 256>>>(acts, labels, act_lens, label_lens);

    size_t smem = (size_t)SMEM_FLOATS * sizeof(float);   // 163,216 B dynamic
    cudaFuncSetAttribute(rnnt_dp_kernel,
                         cudaFuncAttributeMaxDynamicSharedMemorySize, (int)smem);
    rnnt_dp_kernel<<<BB, 128, smem>>>(act_lens, label_lens, out);
}